// round 1
// baseline (speedup 1.0000x reference)
#include <cuda_runtime.h>
#include <math.h>

// Problem constants (fixed shapes)
#define BB   16
#define IC   128
#define OC   128
#define HH   128
#define WW   128
#define EE   16
#define HWSZ (HH*WW)            // 16384
#define KK   9
#define OIK  (OC*IC*KK)         // 147456

// ---------------- device scratch (static, no runtime alloc) ----------------
__device__ float g_p  [BB*IC];                 // pooled x
__device__ float g_rw [BB*EE];                 // routing weights (softmax)
__device__ float g_w  [(size_t)BB*OIK];        // per-sample conv weights  (9.4 MB)
__device__ float g_out[(size_t)BB*OC*HWSZ];    // conv output              (134 MB)
__device__ float g_cp [BB*OC];                 // per-(b,o) sums for SE
__device__ float g_cw [BB*OC];                 // SE channel weights
__device__ float g_mean[BB*HWSZ];              // spatial-attn mean map
__device__ float g_max [BB*HWSZ];              // spatial-attn max map
__device__ float g_sw [BB*HWSZ];               // spatial-attn sigmoid map

__device__ __forceinline__ float bn_scale(float g) {
    return g * rsqrtf(1.0f + 1e-5f);
}
__device__ __forceinline__ float sigmoidf_(float v) {
    return 1.0f / (1.0f + __expf(-v));
}

// ---------------- K1: global average pool of x -> g_p ----------------
__global__ void k_pool(const float* __restrict__ x) {
    int b = blockIdx.x >> 7;
    int c = blockIdx.x & 127;
    const float* p = x + ((size_t)b * IC + c) * HWSZ;
    float s = 0.0f;
    for (int i = threadIdx.x; i < HWSZ; i += 256) s += p[i];
    __shared__ float sm[256];
    sm[threadIdx.x] = s;
    __syncthreads();
    for (int st = 128; st > 0; st >>= 1) {
        if (threadIdx.x < st) sm[threadIdx.x] += sm[threadIdx.x + st];
        __syncthreads();
    }
    if (threadIdx.x == 0) g_p[b * IC + c] = sm[0] * (1.0f / HWSZ);
}

// ---------------- K2: routing MLP + softmax (1 block) ----------------
__global__ void k_route(const float* __restrict__ rw1, const float* __restrict__ g1, const float* __restrict__ b1,
                        const float* __restrict__ rw2, const float* __restrict__ g2, const float* __restrict__ b2,
                        const float* __restrict__ rw3, const float* __restrict__ rb3) {
    __shared__ float sp[BB*IC];
    __shared__ float sh[BB*EE];
    __shared__ float sg[BB*IC];
    __shared__ float sl[BB*EE];
    int t = threadIdx.x;
    for (int i = t; i < BB*IC; i += 256) sp[i] = g_p[i];
    for (int i = t; i < BB*OC; i += 256) g_cp[i] = 0.0f;   // zero SE accumulators
    __syncthreads();
    {   // h = relu(bn(p @ rw1^T))   [16,16]
        int b = t >> 4, j = t & 15;
        float a = 0.0f;
        for (int i = 0; i < IC; i++) a += sp[b*IC + i] * rw1[j*IC + i];
        a = a * bn_scale(g1[j]) + b1[j];
        sh[t] = fmaxf(a, 0.0f);
    }
    __syncthreads();
    for (int k = 0; k < 8; k++) {  // g = sigmoid(bn(h @ rw2^T)) [16,128]
        int idx = t + k*256;
        int b = idx >> 7, i = idx & 127;
        float a = 0.0f;
        for (int j = 0; j < EE; j++) a += sh[b*EE + j] * rw2[i*EE + j];
        a = a * bn_scale(g2[i]) + b2[i];
        sg[idx] = sigmoidf_(a);
    }
    __syncthreads();
    {   // logits = g @ rw3^T + rb3  [16,16]
        int b = t >> 4, e = t & 15;
        float a = rb3[e];
        for (int i = 0; i < IC; i++) a += sg[b*IC + i] * rw3[e*IC + i];
        sl[t] = a;
    }
    __syncthreads();
    {   // softmax over e
        int b = t >> 4;
        float m = -1e30f;
        for (int k = 0; k < EE; k++) m = fmaxf(m, sl[b*EE + k]);
        float s = 0.0f;
        for (int k = 0; k < EE; k++) s += __expf(sl[b*EE + k] - m);
        g_rw[t] = __expf(sl[t] - m) / s;
    }
}

// ---------------- K3: expert-weighted kernel generation ----------------
__global__ void k_wgen(const float* __restrict__ experts) {
    __shared__ float srw[BB*EE];
    int t = threadIdx.x;
    srw[t] = g_rw[t];
    __syncthreads();
    int idx = blockIdx.x * 256 + t;        // 0 .. OIK-1
    float acc[BB];
#pragma unroll
    for (int b = 0; b < BB; b++) acc[b] = 0.0f;
    for (int e = 0; e < EE; e++) {
        float ev = experts[(size_t)e * OIK + idx];
#pragma unroll
        for (int b = 0; b < BB; b++) acc[b] += srw[b*EE + e] * ev;
    }
#pragma unroll
    for (int b = 0; b < BB; b++) g_w[(size_t)b * OIK + idx] = acc[b];
}

// ---------------- K4: per-sample 3x3 conv (main compute) ----------------
// block: 32x32 spatial tile, 16 output channels, one b.
// 256 threads as 16x16; each thread -> 2x2 px * 16 o (64 accumulators).
__global__ void __launch_bounds__(256) k_conv(const float* __restrict__ x) {
    __shared__ float xs[34*34];
    __shared__ float ws[16*9];
    __shared__ float s_cp[16];
    int bz = blockIdx.z;
    int b = bz >> 3;
    int obase = (bz & 7) << 4;
    int h0 = blockIdx.y * 32, w0 = blockIdx.x * 32;
    int tid = threadIdx.x;
    int ty = tid >> 4, tx = tid & 15;

    float acc[16][4];
#pragma unroll
    for (int o = 0; o < 16; o++)
#pragma unroll
        for (int p = 0; p < 4; p++) acc[o][p] = 0.0f;
    if (tid < 16) s_cp[tid] = 0.0f;

    const float* xb = x + (size_t)b * IC * HWSZ;
    const float* wb = g_w + ((size_t)b * OC + obase) * IC * KK;

    for (int ic = 0; ic < IC; ic++) {
        const float* xc = xb + (size_t)ic * HWSZ;
        for (int i = tid; i < 34*34; i += 256) {
            int r = i / 34, c = i - r * 34;
            int hh = h0 - 1 + r, ww = w0 - 1 + c;
            xs[i] = (hh >= 0 && hh < HH && ww >= 0 && ww < WW) ? xc[hh*WW + ww] : 0.0f;
        }
        if (tid < 144) {
            int o = tid / 9, k = tid - o * 9;
            ws[tid] = wb[((size_t)o * IC + ic) * KK + k];
        }
        __syncthreads();

        float xr[4][4];
#pragma unroll
        for (int r = 0; r < 4; r++)
#pragma unroll
            for (int c = 0; c < 4; c++)
                xr[r][c] = xs[(2*ty + r) * 34 + 2*tx + c];

#pragma unroll
        for (int o = 0; o < 16; o++) {
            float w00 = ws[o*9+0], w01 = ws[o*9+1], w02 = ws[o*9+2];
            float w10 = ws[o*9+3], w11 = ws[o*9+4], w12 = ws[o*9+5];
            float w20 = ws[o*9+6], w21 = ws[o*9+7], w22 = ws[o*9+8];
#pragma unroll
            for (int py = 0; py < 2; py++)
#pragma unroll
                for (int px = 0; px < 2; px++) {
                    float v = acc[o][py*2+px];
                    v += xr[py+0][px+0]*w00 + xr[py+0][px+1]*w01 + xr[py+0][px+2]*w02;
                    v += xr[py+1][px+0]*w10 + xr[py+1][px+1]*w11 + xr[py+1][px+2]*w12;
                    v += xr[py+2][px+0]*w20 + xr[py+2][px+1]*w21 + xr[py+2][px+2]*w22;
                    acc[o][py*2+px] = v;
                }
        }
        __syncthreads();
    }

    // write out + per-(b,o) channel sums for SE
    float* ob = g_out + ((size_t)b * OC + obase) * HWSZ;
#pragma unroll
    for (int o = 0; o < 16; o++) {
        float s = acc[o][0] + acc[o][1] + acc[o][2] + acc[o][3];
        // warp-level reduce first to cut smem atomics 32x
        for (int off = 16; off > 0; off >>= 1)
            s += __shfl_down_sync(0xffffffffu, s, off);
        if ((tid & 31) == 0) atomicAdd(&s_cp[o], s);
#pragma unroll
        for (int py = 0; py < 2; py++)
#pragma unroll
            for (int px = 0; px < 2; px++) {
                int h = h0 + 2*ty + py, w = w0 + 2*tx + px;
                ob[(size_t)o * HWSZ + h*WW + w] = acc[o][py*2+px];
            }
    }
    __syncthreads();
    if (tid < 16) atomicAdd(&g_cp[b*OC + obase + tid], s_cp[tid]);
}

// ---------------- K5: SE channel attention MLP (1 block) ----------------
__global__ void k_chattn(const float* __restrict__ w1, const float* __restrict__ g1, const float* __restrict__ b1,
                         const float* __restrict__ w2, const float* __restrict__ g2, const float* __restrict__ b2) {
    __shared__ float scp[BB*OC];
    __shared__ float sh[BB*16];
    int t = threadIdx.x;
    for (int i = t; i < BB*OC; i += 256) scp[i] = g_cp[i] * (1.0f / HWSZ);
    __syncthreads();
    {
        int b = t >> 4, j = t & 15;
        float a = 0.0f;
        for (int i = 0; i < OC; i++) a += scp[b*OC + i] * w1[j*OC + i];
        a = a * bn_scale(g1[j]) + b1[j];
        sh[t] = fmaxf(a, 0.0f);
    }
    __syncthreads();
    for (int k = 0; k < 8; k++) {
        int idx = t + k*256;
        int b = idx >> 7, i = idx & 127;
        float a = 0.0f;
        for (int j = 0; j < 16; j++) a += sh[b*16 + j] * w2[i*16 + j];
        a = a * bn_scale(g2[i]) + b2[i];
        g_cw[idx] = sigmoidf_(a);
    }
}

// ---------------- K6: spatial mean/max over channels of out*cw ----------------
__global__ void k_spstats() {
    __shared__ float scw[OC];
    int blk = blockIdx.x;
    int b = blk >> 6;                        // 64 blocks per batch
    int t = threadIdx.x;
    if (t < OC) scw[t] = g_cw[b*OC + t];
    __syncthreads();
    int hw = (blk & 63) * 256 + t;
    const float* ob = g_out + (size_t)b * OC * HWSZ + hw;
    float s = 0.0f, m = -1e30f;
    for (int o = 0; o < OC; o++) {
        float v = ob[(size_t)o * HWSZ] * scw[o];
        s += v;
        m = fmaxf(m, v);
    }
    g_mean[b*HWSZ + hw] = s * (1.0f / OC);
    g_max [b*HWSZ + hw] = m;
}

// ---------------- K7: 7x7 spatial-attention conv + sigmoid(bn) ----------------
__global__ void k_spconv(const float* __restrict__ saw, const float* __restrict__ sg, const float* __restrict__ sb) {
    __shared__ float sw_[98];
    int t = threadIdx.x;
    if (t < 98) sw_[t] = saw[t];
    __syncthreads();
    int idx = blockIdx.x * 256 + t;
    int b = idx >> 14;
    int hw = idx & 16383;
    int h = hw >> 7, w = hw & 127;
    float a = 0.0f;
    const float* mb = g_mean + (size_t)b * HWSZ;
    const float* xb = g_max  + (size_t)b * HWSZ;
    for (int kh = 0; kh < 7; kh++) {
        int hh = h + kh - 3;
        if (hh < 0 || hh >= HH) continue;
        for (int kw = 0; kw < 7; kw++) {
            int ww = w + kw - 3;
            if (ww < 0 || ww >= WW) continue;
            int o = hh*WW + ww;
            a += mb[o] * sw_[kh*7 + kw] + xb[o] * sw_[49 + kh*7 + kw];
        }
    }
    a = a * bn_scale(sg[0]) + sb[0];
    g_sw[idx] = sigmoidf_(a);
}

// ---------------- K8: final out = conv*cw*sw + x ----------------
__global__ void k_final(const float* __restrict__ x, float* __restrict__ out) {
    size_t i4 = (size_t)blockIdx.x * 256 + threadIdx.x;   // over float4 lanes
    size_t e = i4 * 4;
    int b  = (int)(e >> 21);
    int o  = (int)((e >> 14) & 127);
    int hw = (int)(e & 16383);
    float cw = g_cw[b*OC + o];
    float4 v  = *(const float4*)(g_out + e);
    float4 xv = ((const float4*)x)[i4];
    float4 sv = *(const float4*)(g_sw + (size_t)b*HWSZ + hw);
    float4 r;
    r.x = v.x * cw * sv.x + xv.x;
    r.y = v.y * cw * sv.y + xv.y;
    r.z = v.z * cw * sv.z + xv.z;
    r.w = v.w * cw * sv.w + xv.w;
    ((float4*)out)[i4] = r;
}

// ---------------- launcher ----------------
extern "C" void kernel_launch(void* const* d_in, const int* in_sizes, int n_in,
                              void* d_out, int out_size) {
    const float* x        = (const float*)d_in[0];
    const float* experts  = (const float*)d_in[1];
    const float* rw1      = (const float*)d_in[2];
    const float* rbn1_g   = (const float*)d_in[3];
    const float* rbn1_b   = (const float*)d_in[4];
    const float* rw2      = (const float*)d_in[5];
    const float* rbn2_g   = (const float*)d_in[6];
    const float* rbn2_b   = (const float*)d_in[7];
    const float* rw3      = (const float*)d_in[8];
    const float* rb3      = (const float*)d_in[9];
    const float* ca_w1    = (const float*)d_in[10];
    const float* ca_bn1_g = (const float*)d_in[11];
    const float* ca_bn1_b = (const float*)d_in[12];
    const float* ca_w2    = (const float*)d_in[13];
    const float* ca_bn2_g = (const float*)d_in[14];
    const float* ca_bn2_b = (const float*)d_in[15];
    const float* sa_w     = (const float*)d_in[16];
    const float* sa_bn_g  = (const float*)d_in[17];
    const float* sa_bn_b  = (const float*)d_in[18];
    float* out = (float*)d_out;

    k_pool<<<BB*IC, 256>>>(x);
    k_route<<<1, 256>>>(rw1, rbn1_g, rbn1_b, rw2, rbn2_g, rbn2_b, rw3, rb3);
    k_wgen<<<OIK/256, 256>>>(experts);
    {
        dim3 grid(WW/32, HH/32, BB*8);
        k_conv<<<grid, 256>>>(x);
    }
    k_chattn<<<1, 256>>>(ca_w1, ca_bn1_g, ca_bn1_b, ca_w2, ca_bn2_g, ca_bn2_b);
    k_spstats<<<BB*64, 256>>>();
    k_spconv<<<BB*64, 256>>>(sa_w, sa_bn_g, sa_bn_b);
    k_final<<<(BB*OC*HWSZ)/(4*256), 256>>>(x, out);
}

// round 2
// speedup vs baseline: 1.0012x; 1.0012x over previous
#include <cuda_runtime.h>
#include <math.h>

// Problem constants (fixed shapes)
#define BB   16
#define IC   128
#define OC   128
#define HH   128
#define WW   128
#define EE   16
#define HWSZ (HH*WW)            // 16384
#define KK   9
#define OIK  (OC*IC*KK)         // 147456

// ---------------- device scratch (static, no runtime alloc) ----------------
__device__ float g_p  [BB*IC];                 // pooled x
__device__ float g_rw [BB*EE];                 // routing weights (softmax)
__device__ float g_w  [(size_t)BB*OIK];        // per-sample conv weights  (9.4 MB)
__device__ float g_out[(size_t)BB*OC*HWSZ];    // conv output              (134 MB)
__device__ float g_cp [BB*OC];                 // per-(b,o) sums for SE
__device__ float g_cw [BB*OC];                 // SE channel weights
__device__ float g_mean[BB*HWSZ];              // spatial-attn mean map
__device__ float g_max [BB*HWSZ];              // spatial-attn max map
__device__ float g_sw [BB*HWSZ];               // spatial-attn sigmoid map

__device__ __forceinline__ float bn_scale(float g) {
    return g * rsqrtf(1.0f + 1e-5f);
}
__device__ __forceinline__ float sigmoidf_(float v) {
    return 1.0f / (1.0f + __expf(-v));
}

// ---------------- K1: global average pool of x -> g_p ----------------
__global__ void k_pool(const float* __restrict__ x) {
    int b = blockIdx.x >> 7;
    int c = blockIdx.x & 127;
    const float* p = x + ((size_t)b * IC + c) * HWSZ;
    float s = 0.0f;
    for (int i = threadIdx.x; i < HWSZ; i += 256) s += p[i];
    __shared__ float sm[256];
    sm[threadIdx.x] = s;
    __syncthreads();
    for (int st = 128; st > 0; st >>= 1) {
        if (threadIdx.x < st) sm[threadIdx.x] += sm[threadIdx.x + st];
        __syncthreads();
    }
    if (threadIdx.x == 0) g_p[b * IC + c] = sm[0] * (1.0f / HWSZ);
}

// ---------------- K2: routing MLP + softmax (1 block) ----------------
__global__ void k_route(const float* __restrict__ rw1, const float* __restrict__ g1, const float* __restrict__ b1,
                        const float* __restrict__ rw2, const float* __restrict__ g2, const float* __restrict__ b2,
                        const float* __restrict__ rw3, const float* __restrict__ rb3) {
    __shared__ float sp[BB*IC];
    __shared__ float sh[BB*EE];
    __shared__ float sg[BB*IC];
    __shared__ float sl[BB*EE];
    int t = threadIdx.x;
    for (int i = t; i < BB*IC; i += 256) sp[i] = g_p[i];
    for (int i = t; i < BB*OC; i += 256) g_cp[i] = 0.0f;   // zero SE accumulators
    __syncthreads();
    {   // h = relu(bn(p @ rw1^T))   [16,16]
        int b = t >> 4, j = t & 15;
        float a = 0.0f;
        for (int i = 0; i < IC; i++) a += sp[b*IC + i] * rw1[j*IC + i];
        a = a * bn_scale(g1[j]) + b1[j];
        sh[t] = fmaxf(a, 0.0f);
    }
    __syncthreads();
    for (int k = 0; k < 8; k++) {  // g = sigmoid(bn(h @ rw2^T)) [16,128]
        int idx = t + k*256;
        int b = idx >> 7, i = idx & 127;
        float a = 0.0f;
        for (int j = 0; j < EE; j++) a += sh[b*EE + j] * rw2[i*EE + j];
        a = a * bn_scale(g2[i]) + b2[i];
        sg[idx] = sigmoidf_(a);
    }
    __syncthreads();
    {   // logits = g @ rw3^T + rb3  [16,16]
        int b = t >> 4, e = t & 15;
        float a = rb3[e];
        for (int i = 0; i < IC; i++) a += sg[b*IC + i] * rw3[e*IC + i];
        sl[t] = a;
    }
    __syncthreads();
    {   // softmax over e
        int b = t >> 4;
        float m = -1e30f;
        for (int k = 0; k < EE; k++) m = fmaxf(m, sl[b*EE + k]);
        float s = 0.0f;
        for (int k = 0; k < EE; k++) s += __expf(sl[b*EE + k] - m);
        g_rw[t] = __expf(sl[t] - m) / s;
    }
}

// ---------------- K3: expert-weighted kernel generation ----------------
__global__ void k_wgen(const float* __restrict__ experts) {
    __shared__ float srw[BB*EE];
    int t = threadIdx.x;
    srw[t] = g_rw[t];
    __syncthreads();
    int idx = blockIdx.x * 256 + t;        // 0 .. OIK-1
    float acc[BB];
#pragma unroll
    for (int b = 0; b < BB; b++) acc[b] = 0.0f;
    for (int e = 0; e < EE; e++) {
        float ev = experts[(size_t)e * OIK + idx];
#pragma unroll
        for (int b = 0; b < BB; b++) acc[b] += srw[b*EE + e] * ev;
    }
#pragma unroll
    for (int b = 0; b < BB; b++) g_w[(size_t)b * OIK + idx] = acc[b];
}

// ---------------- K4: per-sample 3x3 conv (main compute) ----------------
// block: 32x32 spatial tile, 16 output channels, one b.
// 256 threads as 16x16; each thread -> 2x2 px * 16 o (64 accumulators).
__global__ void __launch_bounds__(256) k_conv(const float* __restrict__ x) {
    __shared__ float xs[34*34];
    __shared__ float ws[16*9];
    __shared__ float s_cp[16];
    int bz = blockIdx.z;
    int b = bz >> 3;
    int obase = (bz & 7) << 4;
    int h0 = blockIdx.y * 32, w0 = blockIdx.x * 32;
    int tid = threadIdx.x;
    int ty = tid >> 4, tx = tid & 15;

    float acc[16][4];
#pragma unroll
    for (int o = 0; o < 16; o++)
#pragma unroll
        for (int p = 0; p < 4; p++) acc[o][p] = 0.0f;
    if (tid < 16) s_cp[tid] = 0.0f;

    const float* xb = x + (size_t)b * IC * HWSZ;
    const float* wb = g_w + ((size_t)b * OC + obase) * IC * KK;

    for (int ic = 0; ic < IC; ic++) {
        const float* xc = xb + (size_t)ic * HWSZ;
        for (int i = tid; i < 34*34; i += 256) {
            int r = i / 34, c = i - r * 34;
            int hh = h0 - 1 + r, ww = w0 - 1 + c;
            xs[i] = (hh >= 0 && hh < HH && ww >= 0 && ww < WW) ? xc[hh*WW + ww] : 0.0f;
        }
        if (tid < 144) {
            int o = tid / 9, k = tid - o * 9;
            ws[tid] = wb[((size_t)o * IC + ic) * KK + k];
        }
        __syncthreads();

        float xr[4][4];
#pragma unroll
        for (int r = 0; r < 4; r++)
#pragma unroll
            for (int c = 0; c < 4; c++)
                xr[r][c] = xs[(2*ty + r) * 34 + 2*tx + c];

#pragma unroll
        for (int o = 0; o < 16; o++) {
            float w00 = ws[o*9+0], w01 = ws[o*9+1], w02 = ws[o*9+2];
            float w10 = ws[o*9+3], w11 = ws[o*9+4], w12 = ws[o*9+5];
            float w20 = ws[o*9+6], w21 = ws[o*9+7], w22 = ws[o*9+8];
#pragma unroll
            for (int py = 0; py < 2; py++)
#pragma unroll
                for (int px = 0; px < 2; px++) {
                    float v = acc[o][py*2+px];
                    v += xr[py+0][px+0]*w00 + xr[py+0][px+1]*w01 + xr[py+0][px+2]*w02;
                    v += xr[py+1][px+0]*w10 + xr[py+1][px+1]*w11 + xr[py+1][px+2]*w12;
                    v += xr[py+2][px+0]*w20 + xr[py+2][px+1]*w21 + xr[py+2][px+2]*w22;
                    acc[o][py*2+px] = v;
                }
        }
        __syncthreads();
    }

    // write out + per-(b,o) channel sums for SE
    float* ob = g_out + ((size_t)b * OC + obase) * HWSZ;
#pragma unroll
    for (int o = 0; o < 16; o++) {
        float s = acc[o][0] + acc[o][1] + acc[o][2] + acc[o][3];
        // warp-level reduce first to cut smem atomics 32x
        for (int off = 16; off > 0; off >>= 1)
            s += __shfl_down_sync(0xffffffffu, s, off);
        if ((tid & 31) == 0) atomicAdd(&s_cp[o], s);
#pragma unroll
        for (int py = 0; py < 2; py++)
#pragma unroll
            for (int px = 0; px < 2; px++) {
                int h = h0 + 2*ty + py, w = w0 + 2*tx + px;
                ob[(size_t)o * HWSZ + h*WW + w] = acc[o][py*2+px];
            }
    }
    __syncthreads();
    if (tid < 16) atomicAdd(&g_cp[b*OC + obase + tid], s_cp[tid]);
}

// ---------------- K5: SE channel attention MLP (1 block) ----------------
__global__ void k_chattn(const float* __restrict__ w1, const float* __restrict__ g1, const float* __restrict__ b1,
                         const float* __restrict__ w2, const float* __restrict__ g2, const float* __restrict__ b2) {
    __shared__ float scp[BB*OC];
    __shared__ float sh[BB*16];
    int t = threadIdx.x;
    for (int i = t; i < BB*OC; i += 256) scp[i] = g_cp[i] * (1.0f / HWSZ);
    __syncthreads();
    {
        int b = t >> 4, j = t & 15;
        float a = 0.0f;
        for (int i = 0; i < OC; i++) a += scp[b*OC + i] * w1[j*OC + i];
        a = a * bn_scale(g1[j]) + b1[j];
        sh[t] = fmaxf(a, 0.0f);
    }
    __syncthreads();
    for (int k = 0; k < 8; k++) {
        int idx = t + k*256;
        int b = idx >> 7, i = idx & 127;
        float a = 0.0f;
        for (int j = 0; j < 16; j++) a += sh[b*16 + j] * w2[i*16 + j];
        a = a * bn_scale(g2[i]) + b2[i];
        g_cw[idx] = sigmoidf_(a);
    }
}

// ---------------- K6: spatial mean/max over channels of out*cw ----------------
__global__ void k_spstats() {
    __shared__ float scw[OC];
    int blk = blockIdx.x;
    int b = blk >> 6;                        // 64 blocks per batch
    int t = threadIdx.x;
    if (t < OC) scw[t] = g_cw[b*OC + t];
    __syncthreads();
    int hw = (blk & 63) * 256 + t;
    const float* ob = g_out + (size_t)b * OC * HWSZ + hw;
    float s = 0.0f, m = -1e30f;
    for (int o = 0; o < OC; o++) {
        float v = ob[(size_t)o * HWSZ] * scw[o];
        s += v;
        m = fmaxf(m, v);
    }
    g_mean[b*HWSZ + hw] = s * (1.0f / OC);
    g_max [b*HWSZ + hw] = m;
}

// ---------------- K7: 7x7 spatial-attention conv + sigmoid(bn) ----------------
__global__ void k_spconv(const float* __restrict__ saw, const float* __restrict__ sg, const float* __restrict__ sb) {
    __shared__ float sw_[98];
    int t = threadIdx.x;
    if (t < 98) sw_[t] = saw[t];
    __syncthreads();
    int idx = blockIdx.x * 256 + t;
    int b = idx >> 14;
    int hw = idx & 16383;
    int h = hw >> 7, w = hw & 127;
    float a = 0.0f;
    const float* mb = g_mean + (size_t)b * HWSZ;
    const float* xb = g_max  + (size_t)b * HWSZ;
    for (int kh = 0; kh < 7; kh++) {
        int hh = h + kh - 3;
        if (hh < 0 || hh >= HH) continue;
        for (int kw = 0; kw < 7; kw++) {
            int ww = w + kw - 3;
            if (ww < 0 || ww >= WW) continue;
            int o = hh*WW + ww;
            a += mb[o] * sw_[kh*7 + kw] + xb[o] * sw_[49 + kh*7 + kw];
        }
    }
    a = a * bn_scale(sg[0]) + sb[0];
    g_sw[idx] = sigmoidf_(a);
}

// ---------------- K8: final out = conv*cw*sw + x ----------------
__global__ void k_final(const float* __restrict__ x, float* __restrict__ out) {
    size_t i4 = (size_t)blockIdx.x * 256 + threadIdx.x;   // over float4 lanes
    size_t e = i4 * 4;
    int b  = (int)(e >> 21);
    int o  = (int)((e >> 14) & 127);
    int hw = (int)(e & 16383);
    float cw = g_cw[b*OC + o];
    float4 v  = *(const float4*)(g_out + e);
    float4 xv = ((const float4*)x)[i4];
    float4 sv = *(const float4*)(g_sw + (size_t)b*HWSZ + hw);
    float4 r;
    r.x = v.x * cw * sv.x + xv.x;
    r.y = v.y * cw * sv.y + xv.y;
    r.z = v.z * cw * sv.z + xv.z;
    r.w = v.w * cw * sv.w + xv.w;
    ((float4*)out)[i4] = r;
}

// ---------------- launcher ----------------
extern "C" void kernel_launch(void* const* d_in, const int* in_sizes, int n_in,
                              void* d_out, int out_size) {
    const float* x        = (const float*)d_in[0];
    const float* experts  = (const float*)d_in[1];
    const float* rw1      = (const float*)d_in[2];
    const float* rbn1_g   = (const float*)d_in[3];
    const float* rbn1_b   = (const float*)d_in[4];
    const float* rw2      = (const float*)d_in[5];
    const float* rbn2_g   = (const float*)d_in[6];
    const float* rbn2_b   = (const float*)d_in[7];
    const float* rw3      = (const float*)d_in[8];
    const float* rb3      = (const float*)d_in[9];
    const float* ca_w1    = (const float*)d_in[10];
    const float* ca_bn1_g = (const float*)d_in[11];
    const float* ca_bn1_b = (const float*)d_in[12];
    const float* ca_w2    = (const float*)d_in[13];
    const float* ca_bn2_g = (const float*)d_in[14];
    const float* ca_bn2_b = (const float*)d_in[15];
    const float* sa_w     = (const float*)d_in[16];
    const float* sa_bn_g  = (const float*)d_in[17];
    const float* sa_bn_b  = (const float*)d_in[18];
    float* out = (float*)d_out;

    k_pool<<<BB*IC, 256>>>(x);
    k_route<<<1, 256>>>(rw1, rbn1_g, rbn1_b, rw2, rbn2_g, rbn2_b, rw3, rb3);
    k_wgen<<<OIK/256, 256>>>(experts);
    {
        dim3 grid(WW/32, HH/32, BB*8);
        k_conv<<<grid, 256>>>(x);
    }
    k_chattn<<<1, 256>>>(ca_w1, ca_bn1_g, ca_bn1_b, ca_w2, ca_bn2_g, ca_bn2_b);
    k_spstats<<<BB*64, 256>>>();
    k_spconv<<<BB*64, 256>>>(sa_w, sa_bn_g, sa_bn_b);
    k_final<<<(BB*OC*HWSZ)/(4*256), 256>>>(x, out);
}